// round 3
// baseline (speedup 1.0000x reference)
#include <cuda_runtime.h>

#define N_NODES 50000
#define N_EDGES 1600000
#define IN_DIM 6
#define H 64

// Scratch (device globals — no runtime allocation allowed)
__device__ int   g_deg     [N_NODES];
__device__ int   g_rowstart[N_NODES + 1];
__device__ int   g_cursor  [N_NODES];
__device__ int   g_adj     [N_EDGES];
__device__ float g_mean1   [N_NODES * IN_DIM];
__device__ float g_z       [N_NODES * H];
__device__ float g_mean2   [N_NODES * H];

// ---- CSR build ----------------------------------------------------------

__global__ void k_zerodeg() {
    int i = blockIdx.x * blockDim.x + threadIdx.x;
    if (i < N_NODES) g_deg[i] = 0;
}

__global__ void k_count(const int* __restrict__ ei) {
    int e = blockIdx.x * blockDim.x + threadIdx.x;
    if (e >= N_EDGES) return;
    atomicAdd(&g_deg[__ldg(&ei[N_EDGES + e])], 1);
}

// Single-block exclusive scan of g_deg -> g_rowstart / g_cursor
__global__ void k_scan() {
    __shared__ int warpsum[32];
    const int T = 1024;
    int t = threadIdx.x;
    const int CH = (N_NODES + T - 1) / T;  // 49
    int beg = t * CH;
    int end = beg + CH; if (end > N_NODES) end = N_NODES;
    int s = 0;
    for (int i = beg; i < end; i++) s += g_deg[i];
    int lane = t & 31, wid = t >> 5;
    int v = s;
    #pragma unroll
    for (int o = 1; o < 32; o <<= 1) {
        int u = __shfl_up_sync(0xffffffffu, v, o);
        if (lane >= o) v += u;
    }
    if (lane == 31) warpsum[wid] = v;
    __syncthreads();
    if (wid == 0) {
        int w = warpsum[lane];
        #pragma unroll
        for (int o = 1; o < 32; o <<= 1) {
            int u = __shfl_up_sync(0xffffffffu, w, o);
            if (lane >= o) w += u;
        }
        warpsum[lane] = w;
    }
    __syncthreads();
    int run = (v - s) + (wid > 0 ? warpsum[wid - 1] : 0);  // exclusive prefix
    for (int i = beg; i < end; i++) {
        g_rowstart[i] = run;
        g_cursor[i]   = run;
        run += g_deg[i];
    }
    if (t == T - 1) g_rowstart[N_NODES] = run;
}

__global__ void k_scatter(const int* __restrict__ ei) {
    int e = blockIdx.x * blockDim.x + threadIdx.x;
    if (e >= N_EDGES) return;
    int s = __ldg(&ei[e]);
    int d = __ldg(&ei[N_EDGES + e]);
    int pos = atomicAdd(&g_cursor[d], 1);
    g_adj[pos] = s;
}

// ---- Layer 1 ------------------------------------------------------------

// Pull aggregation: mean1[node] = mean of x[neighbors], thread per node
__global__ void k_agg1(const float* __restrict__ x) {
    int node = blockIdx.x * blockDim.x + threadIdx.x;
    if (node >= N_NODES) return;
    int beg = g_rowstart[node], end = g_rowstart[node + 1];
    float a0 = 0, a1 = 0, a2 = 0, a3 = 0, a4 = 0, a5 = 0;
    #pragma unroll 4
    for (int i = beg; i < end; i++) {
        int s = __ldg(&g_adj[i]);
        const float2* xs = reinterpret_cast<const float2*>(x + (size_t)s * IN_DIM);
        float2 p = __ldg(&xs[0]), q = __ldg(&xs[1]), r = __ldg(&xs[2]);
        a0 += p.x; a1 += p.y; a2 += q.x; a3 += q.y; a4 += r.x; a5 += r.y;
    }
    float inv = (end > beg) ? 1.0f / (float)(end - beg) : 0.0f;
    float* m = g_mean1 + (size_t)node * IN_DIM;
    m[0] = a0 * inv; m[1] = a1 * inv; m[2] = a2 * inv;
    m[3] = a3 * inv; m[4] = a4 * inv; m[5] = a5 * inv;
}

// z = relu(mean1 @ W1_l + b1_l + x @ W1_r)
__global__ void k_node1(const float* __restrict__ x,
                        const float* __restrict__ W1l,
                        const float* __restrict__ b1l,
                        const float* __restrict__ W1r) {
    __shared__ float sWl[IN_DIM * H];
    __shared__ float sWr[IN_DIM * H];
    __shared__ float sb[H];
    int t = threadIdx.x;  // 256 threads = 4 nodes x 64 dims
    for (int i = t; i < IN_DIM * H; i += 256) { sWl[i] = W1l[i]; sWr[i] = W1r[i]; }
    if (t < H) sb[t] = b1l[t];
    __syncthreads();

    int node = blockIdx.x * 4 + (t >> 6);
    int j = t & 63;
    if (node >= N_NODES) return;

    float acc = sb[j];
    #pragma unroll
    for (int k = 0; k < IN_DIM; k++) {
        acc += g_mean1[node * IN_DIM + k] * sWl[k * H + j]
             + x[node * IN_DIM + k]       * sWr[k * H + j];
    }
    g_z[node * H + j] = fmaxf(acc, 0.0f);
}

// ---- Layer 2 ------------------------------------------------------------

// Pull aggregation: mean2[node] = mean of z[neighbors]. Warp per node,
// lane l accumulates dims [2l, 2l+1]; neighbor indices loaded coalesced
// then broadcast via shfl.
__global__ void k_agg2() {
    int warp = (blockIdx.x * blockDim.x + threadIdx.x) >> 5;
    if (warp >= N_NODES) return;
    int lane = threadIdx.x & 31;
    int beg = g_rowstart[warp], end = g_rowstart[warp + 1];

    float ax = 0.0f, ay = 0.0f;
    for (int base = beg; base < end; base += 32) {
        int idx = base + lane;
        int sidx = (idx < end) ? __ldg(&g_adj[idx]) : 0;
        int m = end - base; if (m > 32) m = 32;
        int j = 0;
        // unrolled-by-4 body for MLP on the L2 gather
        for (; j + 4 <= m; j += 4) {
            int s0 = __shfl_sync(0xffffffffu, sidx, j + 0);
            int s1 = __shfl_sync(0xffffffffu, sidx, j + 1);
            int s2 = __shfl_sync(0xffffffffu, sidx, j + 2);
            int s3 = __shfl_sync(0xffffffffu, sidx, j + 3);
            float2 v0 = *reinterpret_cast<const float2*>(g_z + (size_t)s0 * H + lane * 2);
            float2 v1 = *reinterpret_cast<const float2*>(g_z + (size_t)s1 * H + lane * 2);
            float2 v2 = *reinterpret_cast<const float2*>(g_z + (size_t)s2 * H + lane * 2);
            float2 v3 = *reinterpret_cast<const float2*>(g_z + (size_t)s3 * H + lane * 2);
            ax += v0.x; ay += v0.y;
            ax += v1.x; ay += v1.y;
            ax += v2.x; ay += v2.y;
            ax += v3.x; ay += v3.y;
        }
        for (; j < m; j++) {
            int s = __shfl_sync(0xffffffffu, sidx, j);
            float2 v = *reinterpret_cast<const float2*>(g_z + (size_t)s * H + lane * 2);
            ax += v.x; ay += v.y;
        }
    }
    int deg = end - beg;
    float inv = (deg > 0) ? 1.0f / (float)deg : 0.0f;
    float2* out = reinterpret_cast<float2*>(g_mean2 + (size_t)warp * H + lane * 2);
    *out = make_float2(ax * inv, ay * inv);
}

// out = mean2 @ W2_l + b2_l + z @ W2_r
__global__ void k_node2(const float* __restrict__ W2l,
                        const float* __restrict__ b2l,
                        const float* __restrict__ W2r,
                        float* __restrict__ out) {
    __shared__ float sWl[H * H];
    __shared__ float sWr[H * H];
    __shared__ float sm[4 * H];
    __shared__ float sz[4 * H];
    int t = threadIdx.x;  // 256 threads = 4 nodes x 64 dims
    for (int i = t; i < H * H; i += 256) { sWl[i] = W2l[i]; sWr[i] = W2r[i]; }

    int node0 = blockIdx.x * 4;
    for (int i = t; i < 4 * H; i += 256) {
        int nn = node0 + (i >> 6);
        int kk = i & 63;
        float zz = 0.0f, mm = 0.0f;
        if (nn < N_NODES) {
            zz = g_z[nn * H + kk];
            mm = g_mean2[nn * H + kk];
        }
        sz[i] = zz; sm[i] = mm;
    }
    __syncthreads();

    int local = t >> 6;
    int j = t & 63;
    int node = node0 + local;
    if (node >= N_NODES) return;

    float acc = b2l[j];
    #pragma unroll 8
    for (int k = 0; k < H; k++) {
        acc += sm[local * H + k] * sWl[k * H + j] + sz[local * H + k] * sWr[k * H + j];
    }
    out[node * H + j] = acc;
}

extern "C" void kernel_launch(void* const* d_in, const int* in_sizes, int n_in,
                              void* d_out, int out_size) {
    const float* x   = (const float*)d_in[0];
    const int*   ei  = (const int*)d_in[1];
    const float* W1l = (const float*)d_in[2];
    const float* b1l = (const float*)d_in[3];
    const float* W1r = (const float*)d_in[4];
    const float* W2l = (const float*)d_in[5];
    const float* b2l = (const float*)d_in[6];
    const float* W2r = (const float*)d_in[7];
    float* out = (float*)d_out;

    // CSR build
    k_zerodeg<<<(N_NODES + 255) / 256, 256>>>();
    k_count  <<<(N_EDGES + 255) / 256, 256>>>(ei);
    k_scan   <<<1, 1024>>>();
    k_scatter<<<(N_EDGES + 255) / 256, 256>>>(ei);
    // layer 1
    k_agg1 <<<(N_NODES + 127) / 128, 128>>>(x);
    k_node1<<<(N_NODES + 3) / 4, 256>>>(x, W1l, b1l, W1r);
    // layer 2
    k_agg2 <<<(N_NODES * 32 + 255) / 256, 256>>>();
    k_node2<<<(N_NODES + 3) / 4, 256>>>(W2l, b2l, W2r, out);
}

// round 4
// speedup vs baseline: 1.3429x; 1.3429x over previous
#include <cuda_runtime.h>

#define N_NODES 50000
#define N_EDGES 1600000
#define IN_DIM 6
#define H 64
#define SCAN_BLOCKS ((N_NODES + 255) / 256)   // 196

// Scratch (device globals — no runtime allocation allowed)
__device__ int   g_deg     [N_NODES];
__device__ int   g_rowstart[N_NODES + 1];
__device__ int   g_cursor  [N_NODES];
__device__ int   g_adj     [N_EDGES];
__device__ int   g_bsum    [SCAN_BLOCKS];
__device__ int   g_boff    [SCAN_BLOCKS];
__device__ float g_mean1   [N_NODES * IN_DIM];
__device__ float g_z       [N_NODES * H];
__device__ float g_mean2   [N_NODES * H];

// ---- CSR build ----------------------------------------------------------

__global__ void k_zerodeg() {
    int i = blockIdx.x * blockDim.x + threadIdx.x;
    if (i < N_NODES) g_deg[i] = 0;
}

__global__ void k_count(const int* __restrict__ ei) {
    int e = blockIdx.x * blockDim.x + threadIdx.x;
    if (e >= N_EDGES) return;
    atomicAdd(&g_deg[__ldg(&ei[N_EDGES + e])], 1);
}

__device__ __forceinline__ int warp_incl_scan(int v, int lane) {
    #pragma unroll
    for (int o = 1; o < 32; o <<= 1) {
        int u = __shfl_up_sync(0xffffffffu, v, o);
        if (lane >= o) v += u;
    }
    return v;
}

// Phase 1: per-block exclusive scan of g_deg -> partial rowstart + block sums
__global__ void k_scan1() {
    __shared__ int ws[8];
    int t = threadIdx.x;
    int i = blockIdx.x * 256 + t;
    int val = (i < N_NODES) ? g_deg[i] : 0;
    int lane = t & 31, w = t >> 5;
    int v = warp_incl_scan(val, lane);
    if (lane == 31) ws[w] = v;
    __syncthreads();
    if (w == 0 && lane < 8) {
        int u = ws[lane];
        #pragma unroll
        for (int o = 1; o < 8; o <<= 1) {
            int p = __shfl_up_sync(0xffu, u, o);
            if (lane >= o) u += p;
        }
        ws[lane] = u;
    }
    __syncthreads();
    int excl = (v - val) + (w > 0 ? ws[w - 1] : 0);
    if (i < N_NODES) g_rowstart[i] = excl;
    if (t == 255) g_bsum[blockIdx.x] = excl + val;
}

// Phase 2: single-block exclusive scan of block sums (SCAN_BLOCKS <= 256)
__global__ void k_scan2() {
    __shared__ int ws[8];
    int t = threadIdx.x;
    int val = (t < SCAN_BLOCKS) ? g_bsum[t] : 0;
    int lane = t & 31, w = t >> 5;
    int v = warp_incl_scan(val, lane);
    if (lane == 31) ws[w] = v;
    __syncthreads();
    if (w == 0 && lane < 8) {
        int u = ws[lane];
        #pragma unroll
        for (int o = 1; o < 8; o <<= 1) {
            int p = __shfl_up_sync(0xffu, u, o);
            if (lane >= o) u += p;
        }
        ws[lane] = u;
    }
    __syncthreads();
    if (t < SCAN_BLOCKS) g_boff[t] = (v - val) + (w > 0 ? ws[w - 1] : 0);
}

// Phase 3: add block offsets, init cursors, close the row pointer
__global__ void k_scan3() {
    int i = blockIdx.x * blockDim.x + threadIdx.x;
    if (i < N_NODES) {
        int r = g_rowstart[i] + g_boff[i >> 8];
        g_rowstart[i] = r;
        g_cursor[i]   = r;
    }
    if (i == 0) g_rowstart[N_NODES] = N_EDGES;
}

// Scatter src ids into CSR buckets (ILP = 2 independent chains per thread)
__global__ void k_scatter(const int* __restrict__ ei) {
    const int HALF = (N_EDGES + 1) / 2;
    int e = blockIdx.x * blockDim.x + threadIdx.x;
    if (e >= HALF) return;
    int s0 = __ldg(&ei[e]);
    int d0 = __ldg(&ei[N_EDGES + e]);
    int e1 = e + HALF;
    int s1 = 0, d1 = 0;
    bool has1 = (e1 < N_EDGES);
    if (has1) { s1 = __ldg(&ei[e1]); d1 = __ldg(&ei[N_EDGES + e1]); }
    int p0 = atomicAdd(&g_cursor[d0], 1);
    int p1 = has1 ? atomicAdd(&g_cursor[d1], 1) : 0;
    g_adj[p0] = s0;
    if (has1) g_adj[p1] = s1;
}

// ---- Layer 1 ------------------------------------------------------------

__global__ void k_agg1(const float* __restrict__ x) {
    int node = blockIdx.x * blockDim.x + threadIdx.x;
    if (node >= N_NODES) return;
    int beg = g_rowstart[node], end = g_rowstart[node + 1];
    float a0 = 0, a1 = 0, a2 = 0, a3 = 0, a4 = 0, a5 = 0;
    #pragma unroll 4
    for (int i = beg; i < end; i++) {
        int s = __ldg(&g_adj[i]);
        const float2* xs = reinterpret_cast<const float2*>(x + (size_t)s * IN_DIM);
        float2 p = __ldg(&xs[0]), q = __ldg(&xs[1]), r = __ldg(&xs[2]);
        a0 += p.x; a1 += p.y; a2 += q.x; a3 += q.y; a4 += r.x; a5 += r.y;
    }
    float inv = (end > beg) ? 1.0f / (float)(end - beg) : 0.0f;
    float* m = g_mean1 + (size_t)node * IN_DIM;
    m[0] = a0 * inv; m[1] = a1 * inv; m[2] = a2 * inv;
    m[3] = a3 * inv; m[4] = a4 * inv; m[5] = a5 * inv;
}

// z = relu(mean1 @ W1_l + b1_l + x @ W1_r), 32 nodes per block
__global__ void k_node1(const float* __restrict__ x,
                        const float* __restrict__ W1l,
                        const float* __restrict__ b1l,
                        const float* __restrict__ W1r) {
    __shared__ float sWl[IN_DIM * H];
    __shared__ float sWr[IN_DIM * H];
    __shared__ float sb[H];
    int t = threadIdx.x;
    for (int i = t; i < IN_DIM * H; i += 256) { sWl[i] = W1l[i]; sWr[i] = W1r[i]; }
    if (t < H) sb[t] = b1l[t];
    __syncthreads();

    int base = blockIdx.x * 32;
    int local = t >> 6;
    int j = t & 63;
    #pragma unroll
    for (int g = 0; g < 8; g++) {
        int node = base + g * 4 + local;
        if (node < N_NODES) {
            float acc = sb[j];
            #pragma unroll
            for (int k = 0; k < IN_DIM; k++) {
                acc += g_mean1[node * IN_DIM + k] * sWl[k * H + j]
                     + x[node * IN_DIM + k]       * sWr[k * H + j];
            }
            g_z[node * H + j] = fmaxf(acc, 0.0f);
        }
    }
}

// ---- Layer 2 ------------------------------------------------------------

// Pull aggregation, 4 warps per node (each takes deg/4 neighbors), smem reduce.
__global__ void k_agg2() {
    __shared__ float red[2][4][H];   // 2 nodes x 4 warps x 64 dims
    int t = threadIdx.x;             // 256 = 2 nodes x 128
    int grp  = t >> 7;
    int t128 = t & 127;
    int wg   = t128 >> 5;
    int lane = t & 31;
    int node = blockIdx.x * 2 + grp;

    float ax = 0.0f, ay = 0.0f;
    int beg = 0, deg = 0;
    if (node < N_NODES) {
        beg = g_rowstart[node];
        deg = g_rowstart[node + 1] - beg;
        int chunk = (deg + 3) >> 2;
        int wbeg = beg + wg * chunk;
        int wend = wbeg + chunk;
        int end  = beg + deg;
        if (wend > end) wend = end;
        for (int base = wbeg; base < wend; base += 32) {
            int idx = base + lane;
            int sidx = (idx < wend) ? __ldg(&g_adj[idx]) : 0;
            int m = wend - base; if (m > 32) m = 32;
            int j = 0;
            for (; j + 4 <= m; j += 4) {
                int s0 = __shfl_sync(0xffffffffu, sidx, j + 0);
                int s1 = __shfl_sync(0xffffffffu, sidx, j + 1);
                int s2 = __shfl_sync(0xffffffffu, sidx, j + 2);
                int s3 = __shfl_sync(0xffffffffu, sidx, j + 3);
                float2 v0 = *reinterpret_cast<const float2*>(g_z + (size_t)s0 * H + lane * 2);
                float2 v1 = *reinterpret_cast<const float2*>(g_z + (size_t)s1 * H + lane * 2);
                float2 v2 = *reinterpret_cast<const float2*>(g_z + (size_t)s2 * H + lane * 2);
                float2 v3 = *reinterpret_cast<const float2*>(g_z + (size_t)s3 * H + lane * 2);
                ax += v0.x + v1.x + v2.x + v3.x;
                ay += v0.y + v1.y + v2.y + v3.y;
            }
            for (; j < m; j++) {
                int s = __shfl_sync(0xffffffffu, sidx, j);
                float2 v = *reinterpret_cast<const float2*>(g_z + (size_t)s * H + lane * 2);
                ax += v.x; ay += v.y;
            }
        }
    }
    red[grp][wg][lane * 2]     = ax;
    red[grp][wg][lane * 2 + 1] = ay;
    __syncthreads();

    if (node < N_NODES && t128 < H) {
        int d = t128;
        float s = red[grp][0][d] + red[grp][1][d] + red[grp][2][d] + red[grp][3][d];
        float inv = (deg > 0) ? 1.0f / (float)deg : 0.0f;   // deg valid: t128<H<128 same grp
        // recompute deg for safety (deg reg only valid in lanes that had node set)
        int dg = g_rowstart[node + 1] - g_rowstart[node];
        inv = (dg > 0) ? 1.0f / (float)dg : 0.0f;
        g_mean2[node * H + d] = s * inv;
    }
}

// out = mean2 @ W2_l + b2_l + z @ W2_r, 32 nodes per block (weights loaded once)
__global__ void k_node2(const float* __restrict__ W2l,
                        const float* __restrict__ b2l,
                        const float* __restrict__ W2r,
                        float* __restrict__ out) {
    __shared__ float sWl[H * H];
    __shared__ float sWr[H * H];
    __shared__ float sb[H];
    __shared__ float sm[4 * H];
    __shared__ float sz[4 * H];
    int t = threadIdx.x;
    for (int i = t; i < H * H; i += 256) { sWl[i] = W2l[i]; sWr[i] = W2r[i]; }
    if (t < H) sb[t] = b2l[t];

    int base = blockIdx.x * 32;
    int local = t >> 6;
    int j = t & 63;
    for (int g = 0; g < 8; g++) {
        int node0 = base + g * 4;
        __syncthreads();
        for (int i = t; i < 4 * H; i += 256) {
            int nn = node0 + (i >> 6);
            int kk = i & 63;
            float zz = 0.0f, mm = 0.0f;
            if (nn < N_NODES) {
                zz = g_z[nn * H + kk];
                mm = g_mean2[nn * H + kk];
            }
            sz[i] = zz; sm[i] = mm;
        }
        __syncthreads();
        int node = node0 + local;
        if (node < N_NODES) {
            float acc = sb[j];
            #pragma unroll 8
            for (int k = 0; k < H; k++) {
                acc += sm[local * H + k] * sWl[k * H + j] + sz[local * H + k] * sWr[k * H + j];
            }
            out[node * H + j] = acc;
        }
    }
}

extern "C" void kernel_launch(void* const* d_in, const int* in_sizes, int n_in,
                              void* d_out, int out_size) {
    const float* x   = (const float*)d_in[0];
    const int*   ei  = (const int*)d_in[1];
    const float* W1l = (const float*)d_in[2];
    const float* b1l = (const float*)d_in[3];
    const float* W1r = (const float*)d_in[4];
    const float* W2l = (const float*)d_in[5];
    const float* b2l = (const float*)d_in[6];
    const float* W2r = (const float*)d_in[7];
    float* out = (float*)d_out;

    // CSR build
    k_zerodeg<<<(N_NODES + 255) / 256, 256>>>();
    k_count  <<<(N_EDGES + 255) / 256, 256>>>(ei);
    k_scan1  <<<SCAN_BLOCKS, 256>>>();
    k_scan2  <<<1, 256>>>();
    k_scan3  <<<SCAN_BLOCKS, 256>>>();
    {
        const int HALF = (N_EDGES + 1) / 2;
        k_scatter<<<(HALF + 255) / 256, 256>>>(ei);
    }
    // layer 1
    k_agg1 <<<(N_NODES + 127) / 128, 128>>>(x);
    k_node1<<<(N_NODES + 31) / 32, 256>>>(x, W1l, b1l, W1r);
    // layer 2
    k_agg2 <<<(N_NODES + 1) / 2, 256>>>();
    k_node2<<<(N_NODES + 31) / 32, 256>>>(W2l, b2l, W2r, out);
}

// round 5
// speedup vs baseline: 1.3908x; 1.0357x over previous
#include <cuda_runtime.h>
#include <cuda_fp16.h>

#define N_NODES 50000
#define N_EDGES 1600000
#define IN_DIM 6
#define H 64
#define SCAN_BLOCKS ((N_NODES + 255) / 256)   // 196

// Scratch (device globals — no runtime allocation allowed)
__device__ int    g_deg     [N_NODES];
__device__ int    g_rowstart[N_NODES + 1];
__device__ int    g_pos     [N_EDGES];
__device__ int    g_adj     [N_EDGES];
__device__ int    g_bsum    [SCAN_BLOCKS];
__device__ int    g_boff    [SCAN_BLOCKS];
__device__ float  g_mean1   [N_NODES * IN_DIM];
__device__ float  g_z       [N_NODES * H];
__device__ __half g_zh      [N_NODES * H];
__device__ float  g_mean2   [N_NODES * H];

// ---- CSR build ----------------------------------------------------------

__global__ void k_zerodeg() {
    int i = blockIdx.x * blockDim.x + threadIdx.x;
    if (i < N_NODES) g_deg[i] = 0;
}

// count + record each edge's rank within its dst bucket
__global__ void k_count(const int* __restrict__ ei) {
    int e = blockIdx.x * blockDim.x + threadIdx.x;
    if (e >= N_EDGES) return;
    int d = __ldg(&ei[N_EDGES + e]);
    g_pos[e] = atomicAdd(&g_deg[d], 1);
}

__device__ __forceinline__ int warp_incl_scan(int v, int lane) {
    #pragma unroll
    for (int o = 1; o < 32; o <<= 1) {
        int u = __shfl_up_sync(0xffffffffu, v, o);
        if (lane >= o) v += u;
    }
    return v;
}

// Phase 1: per-block exclusive scan of g_deg -> partial rowstart + block sums
__global__ void k_scan1() {
    __shared__ int ws[8];
    int t = threadIdx.x;
    int i = blockIdx.x * 256 + t;
    int val = (i < N_NODES) ? g_deg[i] : 0;
    int lane = t & 31, w = t >> 5;
    int v = warp_incl_scan(val, lane);
    if (lane == 31) ws[w] = v;
    __syncthreads();
    if (w == 0 && lane < 8) {
        int u = ws[lane];
        #pragma unroll
        for (int o = 1; o < 8; o <<= 1) {
            int p = __shfl_up_sync(0xffu, u, o);
            if (lane >= o) u += p;
        }
        ws[lane] = u;
    }
    __syncthreads();
    int excl = (v - val) + (w > 0 ? ws[w - 1] : 0);
    if (i < N_NODES) g_rowstart[i] = excl;
    if (t == 255) g_bsum[blockIdx.x] = excl + val;
}

// Phase 2: single-block exclusive scan of block sums (SCAN_BLOCKS <= 256)
__global__ void k_scan2() {
    __shared__ int ws[8];
    int t = threadIdx.x;
    int val = (t < SCAN_BLOCKS) ? g_bsum[t] : 0;
    int lane = t & 31, w = t >> 5;
    int v = warp_incl_scan(val, lane);
    if (lane == 31) ws[w] = v;
    __syncthreads();
    if (w == 0 && lane < 8) {
        int u = ws[lane];
        #pragma unroll
        for (int o = 1; o < 8; o <<= 1) {
            int p = __shfl_up_sync(0xffu, u, o);
            if (lane >= o) u += p;
        }
        ws[lane] = u;
    }
    __syncthreads();
    if (t < SCAN_BLOCKS) g_boff[t] = (v - val) + (w > 0 ? ws[w - 1] : 0);
}

// Phase 3: add block offsets, close the row pointer
__global__ void k_scan3() {
    int i = blockIdx.x * blockDim.x + threadIdx.x;
    if (i < N_NODES) g_rowstart[i] += g_boff[i >> 8];
    if (i == 0) g_rowstart[N_NODES] = N_EDGES;
}

// Atomic-free placement using precomputed ranks
__global__ void k_place(const int* __restrict__ ei) {
    int e = blockIdx.x * blockDim.x + threadIdx.x;
    if (e >= N_EDGES) return;
    int s = __ldg(&ei[e]);
    int d = __ldg(&ei[N_EDGES + e]);
    g_adj[__ldg(&g_rowstart[d]) + g_pos[e]] = s;
}

// ---- Layer 1 ------------------------------------------------------------

__global__ void k_agg1(const float* __restrict__ x) {
    int node = blockIdx.x * blockDim.x + threadIdx.x;
    if (node >= N_NODES) return;
    int beg = g_rowstart[node], end = g_rowstart[node + 1];
    float a0 = 0, a1 = 0, a2 = 0, a3 = 0, a4 = 0, a5 = 0;
    #pragma unroll 4
    for (int i = beg; i < end; i++) {
        int s = __ldg(&g_adj[i]);
        const float2* xs = reinterpret_cast<const float2*>(x + (size_t)s * IN_DIM);
        float2 p = __ldg(&xs[0]), q = __ldg(&xs[1]), r = __ldg(&xs[2]);
        a0 += p.x; a1 += p.y; a2 += q.x; a3 += q.y; a4 += r.x; a5 += r.y;
    }
    float inv = (end > beg) ? 1.0f / (float)(end - beg) : 0.0f;
    float* m = g_mean1 + (size_t)node * IN_DIM;
    m[0] = a0 * inv; m[1] = a1 * inv; m[2] = a2 * inv;
    m[3] = a3 * inv; m[4] = a4 * inv; m[5] = a5 * inv;
}

// z = relu(mean1 @ W1_l + b1_l + x @ W1_r), 32 nodes per block.
// Emits fp32 (for node2 lin_r) and fp16 (for the layer-2 gather).
__global__ void k_node1(const float* __restrict__ x,
                        const float* __restrict__ W1l,
                        const float* __restrict__ b1l,
                        const float* __restrict__ W1r) {
    __shared__ float sWl[IN_DIM * H];
    __shared__ float sWr[IN_DIM * H];
    __shared__ float sb[H];
    int t = threadIdx.x;
    for (int i = t; i < IN_DIM * H; i += 256) { sWl[i] = W1l[i]; sWr[i] = W1r[i]; }
    if (t < H) sb[t] = b1l[t];
    __syncthreads();

    int base = blockIdx.x * 32;
    int local = t >> 6;
    int j = t & 63;
    #pragma unroll
    for (int g = 0; g < 8; g++) {
        int node = base + g * 4 + local;
        if (node < N_NODES) {
            float acc = sb[j];
            #pragma unroll
            for (int k = 0; k < IN_DIM; k++) {
                acc += g_mean1[node * IN_DIM + k] * sWl[k * H + j]
                     + x[node * IN_DIM + k]       * sWr[k * H + j];
            }
            float zv = fmaxf(acc, 0.0f);
            g_z [node * H + j] = zv;
            g_zh[node * H + j] = __float2half(zv);
        }
    }
}

// ---- Layer 2 ------------------------------------------------------------

// Pull aggregation over fp16 z. 4 warps per node; lane covers dims [2l,2l+1]
// via one half2 load (full row = one 128B line per neighbor).
__global__ void k_agg2() {
    __shared__ float red[2][4][H];   // 2 nodes x 4 warps x 64 dims
    int t = threadIdx.x;             // 256 = 2 nodes x 128
    int grp  = t >> 7;
    int t128 = t & 127;
    int wg   = t128 >> 5;
    int lane = t & 31;
    int node = blockIdx.x * 2 + grp;

    float ax = 0.0f, ay = 0.0f;
    if (node < N_NODES) {
        int beg = g_rowstart[node];
        int end = g_rowstart[node + 1];
        int deg = end - beg;
        int chunk = (deg + 3) >> 2;
        int wbeg = beg + wg * chunk;
        int wend = wbeg + chunk;
        if (wend > end) wend = end;
        const __half2* zh = reinterpret_cast<const __half2*>(g_zh);
        for (int base = wbeg; base < wend; base += 32) {
            int idx = base + lane;
            int sidx = (idx < wend) ? __ldg(&g_adj[idx]) : 0;
            int m = wend - base; if (m > 32) m = 32;
            int j = 0;
            for (; j + 4 <= m; j += 4) {
                int s0 = __shfl_sync(0xffffffffu, sidx, j + 0);
                int s1 = __shfl_sync(0xffffffffu, sidx, j + 1);
                int s2 = __shfl_sync(0xffffffffu, sidx, j + 2);
                int s3 = __shfl_sync(0xffffffffu, sidx, j + 3);
                __half2 h0 = zh[(size_t)s0 * (H / 2) + lane];
                __half2 h1 = zh[(size_t)s1 * (H / 2) + lane];
                __half2 h2 = zh[(size_t)s2 * (H / 2) + lane];
                __half2 h3 = zh[(size_t)s3 * (H / 2) + lane];
                float2 f0 = __half22float2(h0);
                float2 f1 = __half22float2(h1);
                float2 f2 = __half22float2(h2);
                float2 f3 = __half22float2(h3);
                ax += f0.x + f1.x + f2.x + f3.x;
                ay += f0.y + f1.y + f2.y + f3.y;
            }
            for (; j < m; j++) {
                int s = __shfl_sync(0xffffffffu, sidx, j);
                float2 f = __half22float2(zh[(size_t)s * (H / 2) + lane]);
                ax += f.x; ay += f.y;
            }
        }
    }
    red[grp][wg][lane * 2]     = ax;
    red[grp][wg][lane * 2 + 1] = ay;
    __syncthreads();

    if (node < N_NODES && t128 < H) {
        int d = t128;
        float s = red[grp][0][d] + red[grp][1][d] + red[grp][2][d] + red[grp][3][d];
        int dg = g_rowstart[node + 1] - g_rowstart[node];
        float inv = (dg > 0) ? 1.0f / (float)dg : 0.0f;
        g_mean2[node * H + d] = s * inv;
    }
}

// out = mean2 @ W2_l + b2_l + z @ W2_r, 32 nodes per block (weights loaded once)
__global__ void k_node2(const float* __restrict__ W2l,
                        const float* __restrict__ b2l,
                        const float* __restrict__ W2r,
                        float* __restrict__ out) {
    __shared__ float sWl[H * H];
    __shared__ float sWr[H * H];
    __shared__ float sb[H];
    __shared__ float sm[4 * H];
    __shared__ float sz[4 * H];
    int t = threadIdx.x;
    for (int i = t; i < H * H; i += 256) { sWl[i] = W2l[i]; sWr[i] = W2r[i]; }
    if (t < H) sb[t] = b2l[t];

    int base = blockIdx.x * 32;
    int local = t >> 6;
    int j = t & 63;
    for (int g = 0; g < 8; g++) {
        int node0 = base + g * 4;
        __syncthreads();
        for (int i = t; i < 4 * H; i += 256) {
            int nn = node0 + (i >> 6);
            int kk = i & 63;
            float zz = 0.0f, mm = 0.0f;
            if (nn < N_NODES) {
                zz = g_z[nn * H + kk];
                mm = g_mean2[nn * H + kk];
            }
            sz[i] = zz; sm[i] = mm;
        }
        __syncthreads();
        int node = node0 + local;
        if (node < N_NODES) {
            float acc = sb[j];
            #pragma unroll 8
            for (int k = 0; k < H; k++) {
                acc += sm[local * H + k] * sWl[k * H + j] + sz[local * H + k] * sWr[k * H + j];
            }
            out[node * H + j] = acc;
        }
    }
}

extern "C" void kernel_launch(void* const* d_in, const int* in_sizes, int n_in,
                              void* d_out, int out_size) {
    const float* x   = (const float*)d_in[0];
    const int*   ei  = (const int*)d_in[1];
    const float* W1l = (const float*)d_in[2];
    const float* b1l = (const float*)d_in[3];
    const float* W1r = (const float*)d_in[4];
    const float* W2l = (const float*)d_in[5];
    const float* b2l = (const float*)d_in[6];
    const float* W2r = (const float*)d_in[7];
    float* out = (float*)d_out;

    // CSR build
    k_zerodeg<<<(N_NODES + 255) / 256, 256>>>();
    k_count  <<<(N_EDGES + 255) / 256, 256>>>(ei);
    k_scan1  <<<SCAN_BLOCKS, 256>>>();
    k_scan2  <<<1, 256>>>();
    k_scan3  <<<SCAN_BLOCKS, 256>>>();
    k_place  <<<(N_EDGES + 255) / 256, 256>>>(ei);
    // layer 1
    k_agg1 <<<(N_NODES + 127) / 128, 128>>>(x);
    k_node1<<<(N_NODES + 31) / 32, 256>>>(x, W1l, b1l, W1r);
    // layer 2
    k_agg2 <<<(N_NODES + 1) / 2, 256>>>();
    k_node2<<<(N_NODES + 31) / 32, 256>>>(W2l, b2l, W2r, out);
}

// round 6
// speedup vs baseline: 1.4485x; 1.0414x over previous
#include <cuda_runtime.h>
#include <cuda_fp16.h>

#define N_NODES 50000
#define N_EDGES 1600000
#define IN_DIM 6
#define H 64
#define SCAN_BLOCKS ((N_NODES + 255) / 256)   // 196

// Scratch (device globals — zero-initialized at load; no runtime allocation)
__device__ int    g_deg     [N_NODES];        // reset to 0 by k_scan3 each launch
__device__ int    g_rowstart[N_NODES + 1];
__device__ int    g_pos     [N_EDGES];
__device__ int    g_adj     [N_EDGES];
__device__ int    g_bsum    [SCAN_BLOCKS];
__device__ int    g_boff    [SCAN_BLOCKS];
__device__ float  g_mean1   [N_NODES * IN_DIM];
__device__ float  g_z       [N_NODES * H];
__device__ __half g_zh      [N_NODES * H];
__device__ float  g_mean2   [N_NODES * H];

// ---- CSR build ----------------------------------------------------------

// count + record each edge's rank within its dst bucket
__global__ void k_count(const int* __restrict__ ei) {
    int e = blockIdx.x * blockDim.x + threadIdx.x;
    if (e >= N_EDGES) return;
    int d = __ldg(&ei[N_EDGES + e]);
    g_pos[e] = atomicAdd(&g_deg[d], 1);
}

__device__ __forceinline__ int warp_incl_scan(int v, int lane) {
    #pragma unroll
    for (int o = 1; o < 32; o <<= 1) {
        int u = __shfl_up_sync(0xffffffffu, v, o);
        if (lane >= o) v += u;
    }
    return v;
}

// Phase 1: per-block exclusive scan of g_deg -> partial rowstart + block sums
__global__ void k_scan1() {
    __shared__ int ws[8];
    int t = threadIdx.x;
    int i = blockIdx.x * 256 + t;
    int val = (i < N_NODES) ? g_deg[i] : 0;
    int lane = t & 31, w = t >> 5;
    int v = warp_incl_scan(val, lane);
    if (lane == 31) ws[w] = v;
    __syncthreads();
    if (w == 0 && lane < 8) {
        int u = ws[lane];
        #pragma unroll
        for (int o = 1; o < 8; o <<= 1) {
            int p = __shfl_up_sync(0xffu, u, o);
            if (lane >= o) u += p;
        }
        ws[lane] = u;
    }
    __syncthreads();
    int excl = (v - val) + (w > 0 ? ws[w - 1] : 0);
    if (i < N_NODES) g_rowstart[i] = excl;
    if (t == 255) g_bsum[blockIdx.x] = excl + val;
}

// Phase 2: single-block exclusive scan of block sums (SCAN_BLOCKS <= 256)
__global__ void k_scan2() {
    __shared__ int ws[8];
    int t = threadIdx.x;
    int val = (t < SCAN_BLOCKS) ? g_bsum[t] : 0;
    int lane = t & 31, w = t >> 5;
    int v = warp_incl_scan(val, lane);
    if (lane == 31) ws[w] = v;
    __syncthreads();
    if (w == 0 && lane < 8) {
        int u = ws[lane];
        #pragma unroll
        for (int o = 1; o < 8; o <<= 1) {
            int p = __shfl_up_sync(0xffu, u, o);
            if (lane >= o) u += p;
        }
        ws[lane] = u;
    }
    __syncthreads();
    if (t < SCAN_BLOCKS) g_boff[t] = (v - val) + (w > 0 ? ws[w - 1] : 0);
}

// Phase 3: add block offsets, close row pointer, and re-arm g_deg for next replay
__global__ void k_scan3() {
    int i = blockIdx.x * blockDim.x + threadIdx.x;
    if (i < N_NODES) {
        g_rowstart[i] += g_boff[i >> 8];
        g_deg[i] = 0;
    }
    if (i == 0) g_rowstart[N_NODES] = N_EDGES;
}

// Atomic-free placement using precomputed ranks
__global__ void k_place(const int* __restrict__ ei) {
    int e = blockIdx.x * blockDim.x + threadIdx.x;
    if (e >= N_EDGES) return;
    int s = __ldg(&ei[e]);
    int d = __ldg(&ei[N_EDGES + e]);
    g_adj[__ldg(&g_rowstart[d]) + g_pos[e]] = s;
}

// ---- Layer 1 ------------------------------------------------------------

__global__ void k_agg1(const float* __restrict__ x) {
    int node = blockIdx.x * blockDim.x + threadIdx.x;
    if (node >= N_NODES) return;
    int beg = g_rowstart[node], end = g_rowstart[node + 1];
    float a0 = 0, a1 = 0, a2 = 0, a3 = 0, a4 = 0, a5 = 0;
    #pragma unroll 4
    for (int i = beg; i < end; i++) {
        int s = __ldg(&g_adj[i]);
        const float2* xs = reinterpret_cast<const float2*>(x + (size_t)s * IN_DIM);
        float2 p = __ldg(&xs[0]), q = __ldg(&xs[1]), r = __ldg(&xs[2]);
        a0 += p.x; a1 += p.y; a2 += q.x; a3 += q.y; a4 += r.x; a5 += r.y;
    }
    float inv = (end > beg) ? 1.0f / (float)(end - beg) : 0.0f;
    float* m = g_mean1 + (size_t)node * IN_DIM;
    m[0] = a0 * inv; m[1] = a1 * inv; m[2] = a2 * inv;
    m[3] = a3 * inv; m[4] = a4 * inv; m[5] = a5 * inv;
}

// z = relu(mean1 @ W1_l + b1_l + x @ W1_r), 32 nodes per block.
__global__ void k_node1(const float* __restrict__ x,
                        const float* __restrict__ W1l,
                        const float* __restrict__ b1l,
                        const float* __restrict__ W1r) {
    __shared__ float sWl[IN_DIM * H];
    __shared__ float sWr[IN_DIM * H];
    __shared__ float sb[H];
    int t = threadIdx.x;
    for (int i = t; i < IN_DIM * H; i += 256) { sWl[i] = W1l[i]; sWr[i] = W1r[i]; }
    if (t < H) sb[t] = b1l[t];
    __syncthreads();

    int base = blockIdx.x * 32;
    int local = t >> 6;
    int j = t & 63;
    #pragma unroll
    for (int g = 0; g < 8; g++) {
        int node = base + g * 4 + local;
        if (node < N_NODES) {
            float acc = sb[j];
            #pragma unroll
            for (int k = 0; k < IN_DIM; k++) {
                acc += g_mean1[node * IN_DIM + k] * sWl[k * H + j]
                     + x[node * IN_DIM + k]       * sWr[k * H + j];
            }
            float zv = fmaxf(acc, 0.0f);
            g_z [node * H + j] = zv;
            g_zh[node * H + j] = __float2half(zv);
        }
    }
}

// ---- Layer 2 ------------------------------------------------------------

__device__ __forceinline__ void acc4(uint2 u, float& a0, float& a1, float& a2, float& a3) {
    __half2 hx = *reinterpret_cast<__half2*>(&u.x);
    __half2 hy = *reinterpret_cast<__half2*>(&u.y);
    float2 fx = __half22float2(hx);
    float2 fy = __half22float2(hy);
    a0 += fx.x; a1 += fx.y; a2 += fy.x; a3 += fy.y;
}

// Pull aggregation over fp16 z. 4 warps per node; each warp load covers TWO
// neighbor rows: lane = (pair-half: lane>=16) x (4-dim group via 8B uint2).
// Unroll 8 neighbors -> 4 independent 8B loads in flight per thread.
__global__ void k_agg2() {
    __shared__ float4 red[2][4][16];  // 2 nodes x 4 warps x 64 dims (as float4)
    int t = threadIdx.x;              // 256 = 2 nodes x 4 warps
    int grp  = t >> 7;
    int t128 = t & 127;
    int wg   = t128 >> 5;
    int lane = t & 31;
    int half = lane >> 4;             // which neighbor of the pair
    int sub  = lane & 15;             // dim group [sub*4, sub*4+4)
    int node = blockIdx.x * 2 + grp;  // N_NODES even: always valid

    int beg = g_rowstart[node];
    int end = g_rowstart[node + 1];
    int deg = end - beg;
    int chunk = (deg + 3) >> 2;
    int wbeg = beg + wg * chunk;
    int wend = wbeg + chunk; if (wend > end) wend = end;

    float a0 = 0, a1 = 0, a2 = 0, a3 = 0;
    const uint2* zh = reinterpret_cast<const uint2*>(g_zh);
    for (int base = wbeg; base < wend; base += 32) {
        int idx = base + lane;
        int sidx = (idx < wend) ? __ldg(&g_adj[idx]) : 0;
        int m = wend - base; if (m > 32) m = 32;
        int j = 0;
        for (; j + 8 <= m; j += 8) {
            int p0 = __shfl_sync(0xffffffffu, sidx, j + 0 + half);
            int p1 = __shfl_sync(0xffffffffu, sidx, j + 2 + half);
            int p2 = __shfl_sync(0xffffffffu, sidx, j + 4 + half);
            int p3 = __shfl_sync(0xffffffffu, sidx, j + 6 + half);
            uint2 u0 = __ldg(&zh[(size_t)p0 * 16 + sub]);
            uint2 u1 = __ldg(&zh[(size_t)p1 * 16 + sub]);
            uint2 u2 = __ldg(&zh[(size_t)p2 * 16 + sub]);
            uint2 u3 = __ldg(&zh[(size_t)p3 * 16 + sub]);
            acc4(u0, a0, a1, a2, a3);
            acc4(u1, a0, a1, a2, a3);
            acc4(u2, a0, a1, a2, a3);
            acc4(u3, a0, a1, a2, a3);
        }
        for (; j + 2 <= m; j += 2) {
            int p = __shfl_sync(0xffffffffu, sidx, j + half);
            uint2 u = __ldg(&zh[(size_t)p * 16 + sub]);
            acc4(u, a0, a1, a2, a3);
        }
        if (j < m) {
            int p = __shfl_sync(0xffffffffu, sidx, j);
            if (half == 0) {
                uint2 u = __ldg(&zh[(size_t)p * 16 + sub]);
                acc4(u, a0, a1, a2, a3);
            }
        }
    }
    // fold the two pair-halves
    a0 += __shfl_xor_sync(0xffffffffu, a0, 16);
    a1 += __shfl_xor_sync(0xffffffffu, a1, 16);
    a2 += __shfl_xor_sync(0xffffffffu, a2, 16);
    a3 += __shfl_xor_sync(0xffffffffu, a3, 16);
    if (half == 0) red[grp][wg][sub] = make_float4(a0, a1, a2, a3);
    __syncthreads();

    if (t128 < H) {
        const float* r = reinterpret_cast<const float*>(red[grp]);
        float s = r[0 * 64 + t128] + r[1 * 64 + t128]
                + r[2 * 64 + t128] + r[3 * 64 + t128];
        float inv = (deg > 0) ? 1.0f / (float)deg : 0.0f;
        g_mean2[node * H + t128] = s * inv;
    }
}

// out = mean2 @ W2_l + b2_l + z @ W2_r, 32 nodes per block (weights loaded once)
__global__ void k_node2(const float* __restrict__ W2l,
                        const float* __restrict__ b2l,
                        const float* __restrict__ W2r,
                        float* __restrict__ out) {
    __shared__ float sWl[H * H];
    __shared__ float sWr[H * H];
    __shared__ float sb[H];
    __shared__ float sm[4 * H];
    __shared__ float sz[4 * H];
    int t = threadIdx.x;
    for (int i = t; i < H * H; i += 256) { sWl[i] = W2l[i]; sWr[i] = W2r[i]; }
    if (t < H) sb[t] = b2l[t];

    int base = blockIdx.x * 32;
    int local = t >> 6;
    int j = t & 63;
    for (int g = 0; g < 8; g++) {
        int node0 = base + g * 4;
        __syncthreads();
        for (int i = t; i < 4 * H; i += 256) {
            int nn = node0 + (i >> 6);
            int kk = i & 63;
            float zz = 0.0f, mm = 0.0f;
            if (nn < N_NODES) {
                zz = g_z[nn * H + kk];
                mm = g_mean2[nn * H + kk];
            }
            sz[i] = zz; sm[i] = mm;
        }
        __syncthreads();
        int node = node0 + local;
        if (node < N_NODES) {
            float acc = sb[j];
            #pragma unroll 8
            for (int k = 0; k < H; k++) {
                acc += sm[local * H + k] * sWl[k * H + j] + sz[local * H + k] * sWr[k * H + j];
            }
            out[node * H + j] = acc;
        }
    }
}

extern "C" void kernel_launch(void* const* d_in, const int* in_sizes, int n_in,
                              void* d_out, int out_size) {
    const float* x   = (const float*)d_in[0];
    const int*   ei  = (const int*)d_in[1];
    const float* W1l = (const float*)d_in[2];
    const float* b1l = (const float*)d_in[3];
    const float* W1r = (const float*)d_in[4];
    const float* W2l = (const float*)d_in[5];
    const float* b2l = (const float*)d_in[6];
    const float* W2r = (const float*)d_in[7];
    float* out = (float*)d_out;

    // CSR build (g_deg starts zeroed: module-load init, then re-armed by k_scan3)
    k_count<<<(N_EDGES + 255) / 256, 256>>>(ei);
    k_scan1<<<SCAN_BLOCKS, 256>>>();
    k_scan2<<<1, 256>>>();
    k_scan3<<<SCAN_BLOCKS, 256>>>();
    k_place<<<(N_EDGES + 255) / 256, 256>>>(ei);
    // layer 1
    k_agg1 <<<(N_NODES + 127) / 128, 128>>>(x);
    k_node1<<<(N_NODES + 31) / 32, 256>>>(x, W1l, b1l, W1r);
    // layer 2
    k_agg2 <<<N_NODES / 2, 256>>>();
    k_node2<<<(N_NODES + 31) / 32, 256>>>(W2l, b2l, W2r, out);
}

// round 7
// speedup vs baseline: 1.5691x; 1.0833x over previous
#include <cuda_runtime.h>
#include <cuda_fp16.h>

#define N_NODES 50000
#define N_EDGES 1600000
#define IN_DIM 6
#define H 64
#define SCAN_BLOCKS ((N_NODES + 255) / 256)   // 196

// Scratch (device globals — zero-initialized at load; no runtime allocation)
__device__ int    g_deg     [N_NODES];        // reset to 0 by k_scan3 each replay
__device__ int    g_rowstart[N_NODES + 1];
__device__ int    g_pos     [N_EDGES];
__device__ int    g_adj     [N_EDGES];
__device__ int    g_bsum    [SCAN_BLOCKS];
__device__ int    g_boff    [SCAN_BLOCKS];
__device__ float  g_mean1   [N_NODES * IN_DIM];
__device__ __half g_uh      [N_NODES * H];    // u = z @ W2_l   (fp16, gather operand)
__device__ float  g_yr      [N_NODES * H];    // yr = z @ W2_r + b2_l

// ---- CSR build ----------------------------------------------------------

__global__ void k_count(const int* __restrict__ ei) {
    int e = blockIdx.x * blockDim.x + threadIdx.x;
    if (e >= N_EDGES) return;
    int d = __ldg(&ei[N_EDGES + e]);
    g_pos[e] = atomicAdd(&g_deg[d], 1);
}

__device__ __forceinline__ int warp_incl_scan(int v, int lane) {
    #pragma unroll
    for (int o = 1; o < 32; o <<= 1) {
        int u = __shfl_up_sync(0xffffffffu, v, o);
        if (lane >= o) v += u;
    }
    return v;
}

__global__ void k_scan1() {
    __shared__ int ws[8];
    int t = threadIdx.x;
    int i = blockIdx.x * 256 + t;
    int val = (i < N_NODES) ? g_deg[i] : 0;
    int lane = t & 31, w = t >> 5;
    int v = warp_incl_scan(val, lane);
    if (lane == 31) ws[w] = v;
    __syncthreads();
    if (w == 0 && lane < 8) {
        int u = ws[lane];
        #pragma unroll
        for (int o = 1; o < 8; o <<= 1) {
            int p = __shfl_up_sync(0xffu, u, o);
            if (lane >= o) u += p;
        }
        ws[lane] = u;
    }
    __syncthreads();
    int excl = (v - val) + (w > 0 ? ws[w - 1] : 0);
    if (i < N_NODES) g_rowstart[i] = excl;
    if (t == 255) g_bsum[blockIdx.x] = excl + val;
}

__global__ void k_scan2() {
    __shared__ int ws[8];
    int t = threadIdx.x;
    int val = (t < SCAN_BLOCKS) ? g_bsum[t] : 0;
    int lane = t & 31, w = t >> 5;
    int v = warp_incl_scan(val, lane);
    if (lane == 31) ws[w] = v;
    __syncthreads();
    if (w == 0 && lane < 8) {
        int u = ws[lane];
        #pragma unroll
        for (int o = 1; o < 8; o <<= 1) {
            int p = __shfl_up_sync(0xffu, u, o);
            if (lane >= o) u += p;
        }
        ws[lane] = u;
    }
    __syncthreads();
    if (t < SCAN_BLOCKS) g_boff[t] = (v - val) + (w > 0 ? ws[w - 1] : 0);
}

__global__ void k_scan3() {
    int i = blockIdx.x * blockDim.x + threadIdx.x;
    if (i < N_NODES) {
        g_rowstart[i] += g_boff[i >> 8];
        g_deg[i] = 0;
    }
    if (i == 0) g_rowstart[N_NODES] = N_EDGES;
}

__global__ void k_place(const int* __restrict__ ei) {
    int e = blockIdx.x * blockDim.x + threadIdx.x;
    if (e >= N_EDGES) return;
    int s = __ldg(&ei[e]);
    int d = __ldg(&ei[N_EDGES + e]);
    g_adj[__ldg(&g_rowstart[d]) + g_pos[e]] = s;
}

// ---- Layer 1 aggregation --------------------------------------------------

__global__ void k_agg1(const float* __restrict__ x) {
    int node = blockIdx.x * blockDim.x + threadIdx.x;
    if (node >= N_NODES) return;
    int beg = g_rowstart[node], end = g_rowstart[node + 1];
    float a0 = 0, a1 = 0, a2 = 0, a3 = 0, a4 = 0, a5 = 0;
    #pragma unroll 4
    for (int i = beg; i < end; i++) {
        int s = __ldg(&g_adj[i]);
        const float2* xs = reinterpret_cast<const float2*>(x + (size_t)s * IN_DIM);
        float2 p = __ldg(&xs[0]), q = __ldg(&xs[1]), r = __ldg(&xs[2]);
        a0 += p.x; a1 += p.y; a2 += q.x; a3 += q.y; a4 += r.x; a5 += r.y;
    }
    float inv = (end > beg) ? 1.0f / (float)(end - beg) : 0.0f;
    float* m = g_mean1 + (size_t)node * IN_DIM;
    m[0] = a0 * inv; m[1] = a1 * inv; m[2] = a2 * inv;
    m[3] = a3 * inv; m[4] = a4 * inv; m[5] = a5 * inv;
}

// ---- Fused node kernel: z = relu(L1), then u = z@W2_l (fp16), yr = z@W2_r + b2_l
__global__ void k_node(const float* __restrict__ x,
                       const float* __restrict__ W1l,
                       const float* __restrict__ b1l,
                       const float* __restrict__ W1r,
                       const float* __restrict__ W2l,
                       const float* __restrict__ b2l,
                       const float* __restrict__ W2r) {
    __shared__ float sW1l[IN_DIM * H];
    __shared__ float sW1r[IN_DIM * H];
    __shared__ float sb1[H];
    __shared__ float sW2l[H * H];
    __shared__ float sW2r[H * H];
    __shared__ float sb2[H];
    __shared__ float sz[32 * H];
    int t = threadIdx.x;
    for (int i = t; i < IN_DIM * H; i += 256) { sW1l[i] = W1l[i]; sW1r[i] = W1r[i]; }
    for (int i = t; i < H * H; i += 256)      { sW2l[i] = W2l[i]; sW2r[i] = W2r[i]; }
    if (t < H) { sb1[t] = b1l[t]; sb2[t] = b2l[t]; }
    __syncthreads();

    int base = blockIdx.x * 32;
    int local = t >> 6;
    int j = t & 63;
    // Phase A: z rows into smem
    #pragma unroll
    for (int g = 0; g < 8; g++) {
        int node = base + g * 4 + local;
        int ln = g * 4 + local;
        float zv = 0.0f;
        if (node < N_NODES) {
            float acc = sb1[j];
            #pragma unroll
            for (int k = 0; k < IN_DIM; k++) {
                acc += g_mean1[node * IN_DIM + k] * sW1l[k * H + j]
                     + x[node * IN_DIM + k]       * sW1r[k * H + j];
            }
            zv = fmaxf(acc, 0.0f);
        }
        sz[ln * H + j] = zv;
    }
    __syncthreads();
    // Phase B: u = z@W2l, yr = z@W2r + b2l
    for (int g = 0; g < 8; g++) {
        int node = base + g * 4 + local;
        if (node < N_NODES) {
            int ln = g * 4 + local;
            float au = 0.0f, ar = sb2[j];
            #pragma unroll 8
            for (int k = 0; k < H; k++) {
                float zv = sz[ln * H + k];
                au += zv * sW2l[k * H + j];
                ar += zv * sW2r[k * H + j];
            }
            g_uh[node * H + j] = __float2half(au);
            g_yr[node * H + j] = ar;
        }
    }
}

// ---- Layer 2 aggregation, fused epilogue: out = mean(u[nbrs]) + yr ---------

__device__ __forceinline__ void acc4(uint2 u, float& a0, float& a1, float& a2, float& a3) {
    __half2 hx = *reinterpret_cast<__half2*>(&u.x);
    __half2 hy = *reinterpret_cast<__half2*>(&u.y);
    float2 fx = __half22float2(hx);
    float2 fy = __half22float2(hy);
    a0 += fx.x; a1 += fx.y; a2 += fy.x; a3 += fy.y;
}

__global__ void k_agg2(float* __restrict__ out) {
    __shared__ float4 red[2][4][16];  // 2 nodes x 4 warps x 64 dims (as float4)
    int t = threadIdx.x;              // 256 = 2 nodes x 4 warps
    int grp  = t >> 7;
    int t128 = t & 127;
    int wg   = t128 >> 5;
    int lane = t & 31;
    int half = lane >> 4;             // which neighbor of the pair
    int sub  = lane & 15;             // dim group [sub*4, sub*4+4)
    int node = blockIdx.x * 2 + grp;  // N_NODES even: always valid

    int beg = g_rowstart[node];
    int end = g_rowstart[node + 1];
    int deg = end - beg;
    int chunk = (deg + 3) >> 2;
    int wbeg = beg + wg * chunk;
    int wend = wbeg + chunk; if (wend > end) wend = end;

    float a0 = 0, a1 = 0, a2 = 0, a3 = 0;
    const uint2* uh = reinterpret_cast<const uint2*>(g_uh);
    for (int base = wbeg; base < wend; base += 32) {
        int idx = base + lane;
        int sidx = (idx < wend) ? __ldg(&g_adj[idx]) : 0;
        int m = wend - base; if (m > 32) m = 32;
        int j = 0;
        for (; j + 8 <= m; j += 8) {
            int p0 = __shfl_sync(0xffffffffu, sidx, j + 0 + half);
            int p1 = __shfl_sync(0xffffffffu, sidx, j + 2 + half);
            int p2 = __shfl_sync(0xffffffffu, sidx, j + 4 + half);
            int p3 = __shfl_sync(0xffffffffu, sidx, j + 6 + half);
            uint2 u0 = __ldg(&uh[(size_t)p0 * 16 + sub]);
            uint2 u1 = __ldg(&uh[(size_t)p1 * 16 + sub]);
            uint2 u2 = __ldg(&uh[(size_t)p2 * 16 + sub]);
            uint2 u3 = __ldg(&uh[(size_t)p3 * 16 + sub]);
            acc4(u0, a0, a1, a2, a3);
            acc4(u1, a0, a1, a2, a3);
            acc4(u2, a0, a1, a2, a3);
            acc4(u3, a0, a1, a2, a3);
        }
        for (; j + 2 <= m; j += 2) {
            int p = __shfl_sync(0xffffffffu, sidx, j + half);
            uint2 u = __ldg(&uh[(size_t)p * 16 + sub]);
            acc4(u, a0, a1, a2, a3);
        }
        if (j < m) {
            int p = __shfl_sync(0xffffffffu, sidx, j);
            if (half == 0) {
                uint2 u = __ldg(&uh[(size_t)p * 16 + sub]);
                acc4(u, a0, a1, a2, a3);
            }
        }
    }
    a0 += __shfl_xor_sync(0xffffffffu, a0, 16);
    a1 += __shfl_xor_sync(0xffffffffu, a1, 16);
    a2 += __shfl_xor_sync(0xffffffffu, a2, 16);
    a3 += __shfl_xor_sync(0xffffffffu, a3, 16);
    if (half == 0) red[grp][wg][sub] = make_float4(a0, a1, a2, a3);
    __syncthreads();

    if (t128 < H) {
        const float* r = reinterpret_cast<const float*>(red[grp]);
        float s = r[0 * 64 + t128] + r[1 * 64 + t128]
                + r[2 * 64 + t128] + r[3 * 64 + t128];
        float inv = (deg > 0) ? 1.0f / (float)deg : 0.0f;
        out[node * H + t128] = s * inv + g_yr[node * H + t128];
    }
}

extern "C" void kernel_launch(void* const* d_in, const int* in_sizes, int n_in,
                              void* d_out, int out_size) {
    const float* x   = (const float*)d_in[0];
    const int*   ei  = (const int*)d_in[1];
    const float* W1l = (const float*)d_in[2];
    const float* b1l = (const float*)d_in[3];
    const float* W1r = (const float*)d_in[4];
    const float* W2l = (const float*)d_in[5];
    const float* b2l = (const float*)d_in[6];
    const float* W2r = (const float*)d_in[7];
    float* out = (float*)d_out;

    // CSR build (g_deg starts zeroed: module-load init, then re-armed by k_scan3)
    k_count<<<(N_EDGES + 255) / 256, 256>>>(ei);
    k_scan1<<<SCAN_BLOCKS, 256>>>();
    k_scan2<<<1, 256>>>();
    k_scan3<<<SCAN_BLOCKS, 256>>>();
    k_place<<<(N_EDGES + 255) / 256, 256>>>(ei);
    // layer 1 aggregation
    k_agg1<<<(N_NODES + 127) / 128, 128>>>(x);
    // fused node transform (layer-1 GEMM + relu + both layer-2 GEMMs)
    k_node<<<(N_NODES + 31) / 32, 256>>>(x, W1l, b1l, W1r, W2l, b2l, W2r);
    // layer-2 aggregation + epilogue
    k_agg2<<<N_NODES / 2, 256>>>(out);
}